// round 7
// baseline (speedup 1.0000x reference)
#include <cuda_runtime.h>
#include <math.h>

#define MAXN 50048
#define MAXE 800000
#define KIN 128
#define HID 64
#define NH 8
#define C2 40
#define NEG 0.2f

// ---------------- scratch (fp32 everywhere) ----------------
__device__ float g_h1[MAXN * HID];
__device__ float g_alS1[MAXN * NH];
__device__ float g_alD1[MAXN * NH];
__device__ float g_hact[MAXN * HID];
__device__ float g_h2[MAXN * C2];
__device__ float g_alS2[MAXN];
__device__ float g_alD2[MAXN];
// CSR
__device__ int g_cnt[MAXN];             // zero at entry (zero-init; scanC re-zeroes)
__device__ int g_incl[MAXN];
__device__ int g_rowstart[MAXN + 1];
__device__ int g_wcur[MAXN];
__device__ int g_eidx[MAXE];
__device__ int g_bsum[64];

// ---------------- CSR build ----------------
__global__ void count_k(const int* __restrict__ ei, int E, int T) {
    int gid = blockIdx.x * blockDim.x + threadIdx.x;
    int i0 = gid, i1 = gid + T, i2 = gid + 2 * T, i3 = gid + 3 * T;
    int d0 = (i0 < E) ? ei[E + i0] : -1;
    int d1 = (i1 < E) ? ei[E + i1] : -1;
    int d2 = (i2 < E) ? ei[E + i2] : -1;
    int d3 = (i3 < E) ? ei[E + i3] : -1;
    if (d0 >= 0) atomicAdd(&g_cnt[d0], 1);
    if (d1 >= 0) atomicAdd(&g_cnt[d1], 1);
    if (d2 >= 0) atomicAdd(&g_cnt[d2], 1);
    if (d3 >= 0) atomicAdd(&g_cnt[d3], 1);
}

__global__ void scanA_k(int n) {
    __shared__ int s[1024];
    int i = blockIdx.x * 1024 + threadIdx.x;
    s[threadIdx.x] = (i < n) ? g_cnt[i] : 0;
    __syncthreads();
#pragma unroll
    for (int o = 1; o < 1024; o <<= 1) {
        int t = 0;
        if (threadIdx.x >= o) t = s[threadIdx.x - o];
        __syncthreads();
        if (threadIdx.x >= o) s[threadIdx.x] += t;
        __syncthreads();
    }
    if (i < n) g_incl[i] = s[threadIdx.x];
    if (threadIdx.x == 1023) g_bsum[blockIdx.x] = s[1023];
}

__global__ void scanC_k(int n, int E, int nb) {
    __shared__ int sb[64];
    int t = threadIdx.x;
    if (t < 64) sb[t] = (t < nb) ? g_bsum[t] : 0;
    __syncthreads();
    int i = blockIdx.x * blockDim.x + t;
    if (i == 0) g_rowstart[n] = E;
    if (i < n) {
        int b = i >> 10;
        int base = 0;
        for (int k = 0; k < b; k++) base += sb[k];
        int start = g_incl[i] - g_cnt[i] + base;
        g_rowstart[i] = start;
        g_wcur[i] = start;
        g_cnt[i] = 0;
    }
}

__global__ void scatter_k(const int* __restrict__ ei, int E, int T) {
    int gid = blockIdx.x * blockDim.x + threadIdx.x;
    int i0 = gid, i1 = gid + T, i2 = gid + 2 * T, i3 = gid + 3 * T;
    int d0 = (i0 < E) ? ei[E + i0] : -1;
    int s0 = (i0 < E) ? ei[i0] : 0;
    int d1 = (i1 < E) ? ei[E + i1] : -1;
    int s1 = (i1 < E) ? ei[i1] : 0;
    int d2 = (i2 < E) ? ei[E + i2] : -1;
    int s2 = (i2 < E) ? ei[i2] : 0;
    int d3 = (i3 < E) ? ei[E + i3] : -1;
    int s3 = (i3 < E) ? ei[i3] : 0;
    int p0 = (d0 >= 0) ? atomicAdd(&g_wcur[d0], 1) : 0;
    int p1 = (d1 >= 0) ? atomicAdd(&g_wcur[d1], 1) : 0;
    int p2 = (d2 >= 0) ? atomicAdd(&g_wcur[d2], 1) : 0;
    int p3 = (d3 >= 0) ? atomicAdd(&g_wcur[d3], 1) : 0;
    if (d0 >= 0) g_eidx[p0] = s0;
    if (d1 >= 0) g_eidx[p1] = s1;
    if (d2 >= 0) g_eidx[p2] = s2;
    if (d3 >= 0) g_eidx[p3] = s3;
}

// ---------------- layer 1 GEMM: register-streamed X, sW-only smem ----------------
// 256 threads, 64 rows/block. Thread t: rows (t>>4)*4..+3, cols (t&15)*4..+3.
// X is NOT staged in smem: each thread streams its 4 rows from gmem as float4
// with a 1-deep prefetch pipeline. smem = 36.8KB -> 4+ blocks/SM.
__global__ __launch_bounds__(256) void gemm1_k(
        const float* __restrict__ x, const float* __restrict__ topo,
        const float* __restrict__ W1,
        const float* __restrict__ a_src, const float* __restrict__ a_dst, int n) {
    __shared__ float sW[KIN * HID];    // 32 KB
    __shared__ float sLS[64 * 8];      // 2 KB
    __shared__ float sLD[64 * 8];      // 2 KB
    int t = threadIdx.x;
    int row0 = blockIdx.x * 64;
    {
        const float4* W14 = reinterpret_cast<const float4*>(W1);
        float4* sW4w = reinterpret_cast<float4*>(sW);
        for (int i = t; i < KIN * HID / 4; i += 256) sW4w[i] = W14[i];
    }
    for (int i = t; i < 512; i += 256) { sLS[i] = 0.f; sLD[i] = 0.f; }

    int rg = t >> 4;
    int cg = t & 15;
    int r0 = row0 + rg * 4;
    bool v[4];
    const float4* xr[4];
    const float4* tr[4];
#pragma unroll
    for (int r = 0; r < 4; r++) {
        int gr = r0 + r;
        v[r] = gr < n;
        int gs = v[r] ? gr : 0;
        xr[r] = reinterpret_cast<const float4*>(x + gs * 120);
        tr[r] = reinterpret_cast<const float4*>(topo + gs * 8);
    }
    __syncthreads();

    float acc[4][4];
#pragma unroll
    for (int r = 0; r < 4; r++)
#pragma unroll
        for (int c = 0; c < 4; c++) acc[r][c] = 0.f;

    const float4 Z = make_float4(0.f, 0.f, 0.f, 0.f);
    float4 cur[4], nxt[4];
#pragma unroll
    for (int r = 0; r < 4; r++) cur[r] = v[r] ? __ldg(&xr[r][0]) : Z;

    const float4* sW4 = reinterpret_cast<const float4*>(sW);
    for (int kq = 0; kq < 32; kq++) {
        // prefetch next chunk
        if (kq < 31) {
            int q = kq + 1;
#pragma unroll
            for (int r = 0; r < 4; r++) {
                if (!v[r]) { nxt[r] = Z; continue; }
                nxt[r] = (q < 30) ? __ldg(&xr[r][q]) : __ldg(&tr[r][q - 30]);
            }
        }
        float xk[4][4];
#pragma unroll
        for (int r = 0; r < 4; r++) {
            xk[r][0] = cur[r].x; xk[r][1] = cur[r].y;
            xk[r][2] = cur[r].z; xk[r][3] = cur[r].w;
        }
#pragma unroll
        for (int kk = 0; kk < 4; kk++) {
            float4 wv = sW4[(kq * 4 + kk) * 16 + cg];
#pragma unroll
            for (int r = 0; r < 4; r++) {
                acc[r][0] += xk[r][kk] * wv.x;
                acc[r][1] += xk[r][kk] * wv.y;
                acc[r][2] += xk[r][kk] * wv.z;
                acc[r][3] += xk[r][kk] * wv.w;
            }
        }
#pragma unroll
        for (int r = 0; r < 4; r++) cur[r] = nxt[r];
    }

    int hd = cg >> 1;
    int off = (cg & 1) * 4;
    float4* g_h1_4 = reinterpret_cast<float4*>(g_h1);
#pragma unroll
    for (int r = 0; r < 4; r++) {
        int lr = rg * 4 + r;
        int gr = row0 + lr;
        if (v[r]) {
            float4 o;
            o.x = acc[r][0]; o.y = acc[r][1]; o.z = acc[r][2]; o.w = acc[r][3];
            g_h1_4[gr * 16 + cg] = o;
        }
        float ps = 0.f, pd = 0.f;
#pragma unroll
        for (int j = 0; j < 4; j++) {
            ps += acc[r][j] * a_src[hd * 8 + off + j];
            pd += acc[r][j] * a_dst[hd * 8 + off + j];
        }
        atomicAdd(&sLS[lr * 8 + hd], ps);
        atomicAdd(&sLD[lr * 8 + hd], pd);
    }
    __syncthreads();
    for (int i = t; i < 512; i += 256) {
        int lr = i >> 3, h = i & 7;
        int gr = row0 + lr;
        if (gr < n) {
            g_alS1[gr * 8 + h] = sLS[i];
            g_alD1[gr * 8 + h] = sLD[i];
        }
    }
}

// ---------------- layer 1 aggregation: warp/node, 4 edges per iteration (R5, fp32) ----------------
__global__ __launch_bounds__(256) void agg1_k(const float* __restrict__ b1, int n) {
    int w = (blockIdx.x * blockDim.x + threadIdx.x) >> 5;
    if (w >= n) return;
    int l = threadIdx.x & 31;
    int h0 = l >> 3;
    int hh = l & 7;
    float alDh = g_alD1[w * 8 + hh];
    int beg = g_rowstart[w], end = g_rowstart[w + 1];
    float acc0 = 0.f, acc1 = 0.f, qsum = 0.f;
    // self loop
    {
        float a = g_alS1[w * 8 + hh] + alDh;
        a = a > 0.f ? a : NEG * a;
        float q = __expf(a);
        if (l < 8) qsum += q;
        float p0 = __shfl_sync(0xFFFFFFFFu, q, h0);
        float p1 = __shfl_sync(0xFFFFFFFFu, q, h0 + 4);
        acc0 += p0 * g_h1[w * HID + l];
        acc1 += p1 * g_h1[w * HID + 32 + l];
    }
    for (int j = beg; j < end; j += 4) {
        int jj = j + h0;
        bool valid = jj < end;
        int srcv = g_eidx[valid ? jj : j];
        float a = g_alS1[srcv * 8 + hh] + alDh;
        a = a > 0.f ? a : NEG * a;
        float q = valid ? __expf(a) : 0.f;
        qsum += q;
        int nleft = end - j;
#pragma unroll
        for (int e2 = 0; e2 < 4; e2++) {
            if (e2 >= nleft) break;
            float p0 = __shfl_sync(0xFFFFFFFFu, q, e2 * 8 + h0);
            float p1 = __shfl_sync(0xFFFFFFFFu, q, e2 * 8 + h0 + 4);
            int sv = __shfl_sync(0xFFFFFFFFu, srcv, e2 * 8);
            acc0 += p0 * g_h1[sv * HID + l];
            acc1 += p1 * g_h1[sv * HID + 32 + l];
        }
    }
    qsum += __shfl_xor_sync(0xFFFFFFFFu, qsum, 8);
    qsum += __shfl_xor_sync(0xFFFFFFFFu, qsum, 16);
    float s0 = __shfl_sync(0xFFFFFFFFu, qsum, h0);
    float s1 = __shfl_sync(0xFFFFFFFFu, qsum, h0 + 4);
    float v0 = acc0 / s0 + b1[l];
    float v1 = acc1 / s1 + b1[32 + l];
    g_hact[w * HID + l]      = v0 > 0.f ? v0 : expm1f(v0);
    g_hact[w * HID + 32 + l] = v1 > 0.f ? v1 : expm1f(v1);
}

// ---------------- layer 2 GEMM: [N,64]@[64,40] + scalar logits ----------------
__global__ __launch_bounds__(160) void gemm2_k(
        const float* __restrict__ W2,
        const float* __restrict__ a_src2, const float* __restrict__ a_dst2, int n) {
    __shared__ float sW[HID * C2];
    __shared__ float sX[64 * HID];
    __shared__ float sLS[64];
    __shared__ float sLD[64];
    int t = threadIdx.x;
    int row0 = blockIdx.x * 64;
    for (int i = t; i < HID * C2; i += 160) sW[i] = W2[i];
    for (int i = t; i < 64 * HID; i += 160) {
        int r = i >> 6, c = i & 63;
        int gr = row0 + r;
        sX[i] = (gr < n) ? g_hact[gr * HID + c] : 0.f;
    }
    if (t < 64) { sLS[t] = 0.f; sLD[t] = 0.f; }
    __syncthreads();

    int cg = t % 10;
    int rg = t / 10;
    float acc[4][4];
#pragma unroll
    for (int r = 0; r < 4; r++)
#pragma unroll
        for (int c = 0; c < 4; c++) acc[r][c] = 0.f;

    const float4* sW4 = reinterpret_cast<const float4*>(sW);
#pragma unroll 4
    for (int k = 0; k < HID; k++) {
        float4 wv = sW4[k * 10 + cg];
        float xv0 = sX[(rg * 4 + 0) * HID + k];
        float xv1 = sX[(rg * 4 + 1) * HID + k];
        float xv2 = sX[(rg * 4 + 2) * HID + k];
        float xv3 = sX[(rg * 4 + 3) * HID + k];
#define STEP(r, xv) \
        acc[r][0] += xv * wv.x; acc[r][1] += xv * wv.y; \
        acc[r][2] += xv * wv.z; acc[r][3] += xv * wv.w;
        STEP(0, xv0) STEP(1, xv1) STEP(2, xv2) STEP(3, xv3)
#undef STEP
    }

#pragma unroll
    for (int r = 0; r < 4; r++) {
        int lr = rg * 4 + r;
        int gr = row0 + lr;
        float ps = 0.f, pd = 0.f;
#pragma unroll
        for (int j = 0; j < 4; j++) {
            int c = cg * 4 + j;
            if (gr < n) g_h2[gr * C2 + c] = acc[r][j];
            ps += acc[r][j] * a_src2[c];
            pd += acc[r][j] * a_dst2[c];
        }
        atomicAdd(&sLS[lr], ps);
        atomicAdd(&sLD[lr], pd);
    }
    __syncthreads();
    if (t < 64) {
        int gr = row0 + t;
        if (gr < n) { g_alS2[gr] = sLS[t]; g_alD2[gr] = sLD[t]; }
    }
}

// ---------------- layer 2 aggregation + log_softmax: warp/node, 32 edges/iter (R5, fp32) ----------------
__global__ __launch_bounds__(256) void agg2_k(const float* __restrict__ b2,
                                              float* __restrict__ out, int n) {
    int w = (blockIdx.x * blockDim.x + threadIdx.x) >> 5;
    if (w >= n) return;
    int l = threadIdx.x & 31;
    float alDv = g_alD2[w];
    int beg = g_rowstart[w], end = g_rowstart[w + 1];
    float acc0 = 0.f, acc1 = 0.f, ssum = 0.f;
    // self loop
    {
        float e = g_alS2[w] + alDv;
        e = e > 0.f ? e : NEG * e;
        float p = __expf(e);
        if (l == 0) ssum += p;
        acc0 += p * g_h2[w * C2 + l];
        if (l < 8) acc1 += p * g_h2[w * C2 + 32 + l];
    }
    for (int j = beg; j < end; j += 32) {
        int jj = j + l;
        bool valid = jj < end;
        int srcv = g_eidx[valid ? jj : j];
        float e = g_alS2[srcv] + alDv;
        e = e > 0.f ? e : NEG * e;
        float q = valid ? __expf(e) : 0.f;
        ssum += q;
        int m = min(32, end - j);
        for (int e2 = 0; e2 < m; e2++) {
            float pp = __shfl_sync(0xFFFFFFFFu, q, e2);
            int sv = __shfl_sync(0xFFFFFFFFu, srcv, e2);
            acc0 += pp * g_h2[sv * C2 + l];
            if (l < 8) acc1 += pp * g_h2[sv * C2 + 32 + l];
        }
    }
#pragma unroll
    for (int o = 16; o; o >>= 1) ssum += __shfl_xor_sync(0xFFFFFFFFu, ssum, o);
    float inv = 1.f / ssum;
    float v0 = acc0 * inv + b2[l];
    float v1 = (l < 8) ? (acc1 * inv + b2[32 + l]) : -3.0e38f;
    float m = fmaxf(v0, v1);
#pragma unroll
    for (int o = 16; o; o >>= 1) m = fmaxf(m, __shfl_xor_sync(0xFFFFFFFFu, m, o));
    float se = __expf(v0 - m) + ((l < 8) ? __expf(v1 - m) : 0.f);
#pragma unroll
    for (int o = 16; o; o >>= 1) se += __shfl_xor_sync(0xFFFFFFFFu, se, o);
    float lse = logf(se) + m;
    out[w * C2 + l] = v0 - lse;
    if (l < 8) out[w * C2 + 32 + l] = v1 - lse;
}

// ---------------- launcher ----------------
extern "C" void kernel_launch(void* const* d_in, const int* in_sizes, int n_in,
                              void* d_out, int out_size) {
    const float* x    = (const float*)d_in[0];
    const float* topo = (const float*)d_in[1];
    const int*   ei   = (const int*)d_in[2];
    const float* W1   = (const float*)d_in[3];
    const float* a_s1 = (const float*)d_in[4];
    const float* a_d1 = (const float*)d_in[5];
    const float* b1   = (const float*)d_in[6];
    const float* W2   = (const float*)d_in[7];
    const float* a_s2 = (const float*)d_in[8];
    const float* a_d2 = (const float*)d_in[9];
    const float* b2   = (const float*)d_in[10];
    float* out = (float*)d_out;

    int n = in_sizes[0] / 120;
    int E = in_sizes[2] / 2;
    int nb = (n + 1023) >> 10;
    int T = (E + 3) / 4;

    // order chosen so ncu's sampled slot (4th launch) == gemm1_k
    count_k<<<(T + 255) / 256, 256>>>(ei, E, T);
    scanA_k<<<nb, 1024>>>(n);
    scanC_k<<<(n + 255) / 256, 256>>>(n, E, nb);
    gemm1_k<<<(n + 63) / 64, 256>>>(x, topo, W1, a_s1, a_d1, n);
    scatter_k<<<(T + 255) / 256, 256>>>(ei, E, T);
    agg1_k<<<(n * 32 + 255) / 256, 256>>>(b1, n);
    gemm2_k<<<(n + 63) / 64, 160>>>(W2, a_s2, a_d2, n);
    agg2_k<<<(n * 32 + 255) / 256, 256>>>(b2, out, n);
}

// round 8
// speedup vs baseline: 1.2344x; 1.2344x over previous
#include <cuda_runtime.h>
#include <math.h>

#define MAXN 50048
#define MAXE 800000
#define KIN 128
#define HID 64
#define NH 8
#define C2 40
#define NEG 0.2f
#define SXCH 36   // chunk row stride in floats (16B-aligned, conflict-free)

// ---------------- scratch (fp32 everywhere) ----------------
__device__ float g_h1[MAXN * HID];
__device__ float g_alS1[MAXN * NH];
__device__ float g_alD1[MAXN * NH];
__device__ float g_hact[MAXN * HID];
__device__ float g_h2[MAXN * C2];
__device__ float g_alS2[MAXN];
__device__ float g_alD2[MAXN];
// CSR
__device__ int g_cnt[MAXN];             // zero at entry (zero-init; scanC re-zeroes)
__device__ int g_incl[MAXN];
__device__ int g_rowstart[MAXN + 1];
__device__ int g_wcur[MAXN];
__device__ int g_eidx[MAXE];
__device__ int g_bsum[64];

__device__ __forceinline__ unsigned smem_u32(const void* p) {
    unsigned a;
    asm("{ .reg .u64 t; cvta.to.shared.u64 t, %1; cvt.u32.u64 %0, t; }" : "=r"(a) : "l"(p));
    return a;
}

// ---------------- CSR build (simple 1 edge / thread — exact) ----------------
__global__ void count_k(const int* __restrict__ ei, int E) {
    int i = blockIdx.x * blockDim.x + threadIdx.x;
    if (i < E) atomicAdd(&g_cnt[ei[E + i]], 1);
}

__global__ void scanA_k(int n) {
    __shared__ int s[1024];
    int i = blockIdx.x * 1024 + threadIdx.x;
    s[threadIdx.x] = (i < n) ? g_cnt[i] : 0;
    __syncthreads();
#pragma unroll
    for (int o = 1; o < 1024; o <<= 1) {
        int t = 0;
        if (threadIdx.x >= o) t = s[threadIdx.x - o];
        __syncthreads();
        if (threadIdx.x >= o) s[threadIdx.x] += t;
        __syncthreads();
    }
    if (i < n) g_incl[i] = s[threadIdx.x];
    if (threadIdx.x == 1023) g_bsum[blockIdx.x] = s[1023];
}

__global__ void scanC_k(int n, int E, int nb) {
    __shared__ int sb[64];
    int t = threadIdx.x;
    if (t < 64) sb[t] = (t < nb) ? g_bsum[t] : 0;
    __syncthreads();
    int i = blockIdx.x * blockDim.x + t;
    if (i == 0) g_rowstart[n] = E;
    if (i < n) {
        int b = i >> 10;
        int base = 0;
        for (int k = 0; k < b; k++) base += sb[k];
        int start = g_incl[i] - g_cnt[i] + base;
        g_rowstart[i] = start;
        g_wcur[i] = start;
        g_cnt[i] = 0;
    }
}

__global__ void scatter_k(const int* __restrict__ ei, int E) {
    int i = blockIdx.x * blockDim.x + threadIdx.x;
    if (i < E) {
        int dst = ei[E + i];
        int pos = atomicAdd(&g_wcur[dst], 1);
        g_eidx[pos] = ei[i];
    }
}

// ---------------- layer 1 GEMM: cp.async double-buffered chunked-K ----------------
// 256 threads, 64 rows x 64 cols, 4x4/thread. W resident in smem; X streamed in
// 32-k chunks via cp.async with 2 buffers. smem ~54KB -> 4 blocks/SM.
__global__ __launch_bounds__(256) void gemm1_k(
        const float* __restrict__ x, const float* __restrict__ topo,
        const float* __restrict__ W1,
        const float* __restrict__ a_src, const float* __restrict__ a_dst, int n) {
    extern __shared__ float smem[];
    float* sW  = smem;                        // 8192 floats
    float* sX0 = smem + 8192;                 // 64*36
    float* sX1 = sX0 + 64 * SXCH;             // 64*36
    float* sLS = sX1 + 64 * SXCH;             // 512
    float* sLD = sLS + 512;                   // 512
    int t = threadIdx.x;
    int row0 = blockIdx.x * 64;

    {
        const float4* W14 = reinterpret_cast<const float4*>(W1);
        float4* sW4w = reinterpret_cast<float4*>(sW);
        for (int i = t; i < KIN * HID / 4; i += 256) sW4w[i] = W14[i];
    }
    for (int i = t; i < 512; i += 256) { sLS[i] = 0.f; sLD[i] = 0.f; }

    // per-thread copy slots: i = t and t+256, each one float4 of the chunk
    int rA = t >> 3, qA = t & 7;
    int rB = (t + 256) >> 3, qB = (t + 256) & 7;
    int gsA = (row0 + rA < n) ? row0 + rA : 0;
    int gsB = (row0 + rB < n) ? row0 + rB : 0;
    const float4* xA = reinterpret_cast<const float4*>(x + gsA * 120);
    const float4* tA = reinterpret_cast<const float4*>(topo + gsA * 8);
    const float4* xB = reinterpret_cast<const float4*>(x + gsB * 120);
    const float4* tB = reinterpret_cast<const float4*>(topo + gsB * 8);
    unsigned dA0 = smem_u32(sX0 + rA * SXCH + qA * 4);
    unsigned dB0 = smem_u32(sX0 + rB * SXCH + qB * 4);
    unsigned dA1 = smem_u32(sX1 + rA * SXCH + qA * 4);
    unsigned dB1 = smem_u32(sX1 + rB * SXCH + qB * 4);

#define ISSUE_CHUNK(kc, dA, dB)                                              \
    {                                                                        \
        const float4* sA = ((kc) < 3) ? (xA + (kc) * 8 + qA)                 \
                          : ((qA < 6) ? (xA + 24 + qA) : (tA + (qA - 6)));   \
        const float4* sB = ((kc) < 3) ? (xB + (kc) * 8 + qB)                 \
                          : ((qB < 6) ? (xB + 24 + qB) : (tB + (qB - 6)));   \
        asm volatile("cp.async.cg.shared.global [%0], [%1], 16;\n"           \
                     :: "r"(dA), "l"(sA) : "memory");                        \
        asm volatile("cp.async.cg.shared.global [%0], [%1], 16;\n"           \
                     :: "r"(dB), "l"(sB) : "memory");                        \
        asm volatile("cp.async.commit_group;\n" ::: "memory");               \
    }

    ISSUE_CHUNK(0, dA0, dB0)

    int rg = t >> 4;
    int cg = t & 15;
    float acc[4][4];
#pragma unroll
    for (int r = 0; r < 4; r++)
#pragma unroll
        for (int c = 0; c < 4; c++) acc[r][c] = 0.f;

    const float4* sW4 = reinterpret_cast<const float4*>(sW);
#pragma unroll
    for (int kc = 0; kc < 4; kc++) {
        if (kc == 0)      ISSUE_CHUNK(1, dA1, dB1)
        else if (kc == 1) ISSUE_CHUNK(2, dA0, dB0)
        else if (kc == 2) ISSUE_CHUNK(3, dA1, dB1)
        if (kc < 3) asm volatile("cp.async.wait_group 1;\n" ::: "memory");
        else        asm volatile("cp.async.wait_group 0;\n" ::: "memory");
        __syncthreads();
        const float* bx = (kc & 1) ? sX1 : sX0;
#pragma unroll 8
        for (int k = 0; k < 32; k++) {
            float4 wv = sW4[(kc * 32 + k) * 16 + cg];
            float xv0 = bx[(rg * 4 + 0) * SXCH + k];
            float xv1 = bx[(rg * 4 + 1) * SXCH + k];
            float xv2 = bx[(rg * 4 + 2) * SXCH + k];
            float xv3 = bx[(rg * 4 + 3) * SXCH + k];
#define STEP(r, xv) \
            acc[r][0] += xv * wv.x; acc[r][1] += xv * wv.y; \
            acc[r][2] += xv * wv.z; acc[r][3] += xv * wv.w;
            STEP(0, xv0) STEP(1, xv1) STEP(2, xv2) STEP(3, xv3)
#undef STEP
        }
        __syncthreads();
    }
#undef ISSUE_CHUNK

    int hd = cg >> 1;
    int off = (cg & 1) * 4;
    float4* g_h1_4 = reinterpret_cast<float4*>(g_h1);
#pragma unroll
    for (int r = 0; r < 4; r++) {
        int lr = rg * 4 + r;
        int gr = row0 + lr;
        if (gr < n) {
            float4 o;
            o.x = acc[r][0]; o.y = acc[r][1]; o.z = acc[r][2]; o.w = acc[r][3];
            g_h1_4[gr * 16 + cg] = o;
        }
        float ps = 0.f, pd = 0.f;
#pragma unroll
        for (int j = 0; j < 4; j++) {
            ps += acc[r][j] * a_src[hd * 8 + off + j];
            pd += acc[r][j] * a_dst[hd * 8 + off + j];
        }
        atomicAdd(&sLS[lr * 8 + hd], ps);
        atomicAdd(&sLD[lr * 8 + hd], pd);
    }
    __syncthreads();
    for (int i = t; i < 512; i += 256) {
        int lr = i >> 3, h = i & 7;
        int gr = row0 + lr;
        if (gr < n) {
            g_alS1[gr * 8 + h] = sLS[i];
            g_alD1[gr * 8 + h] = sLD[i];
        }
    }
}

// ---------------- layer 1 aggregation (R5, fp32) ----------------
__global__ __launch_bounds__(256) void agg1_k(const float* __restrict__ b1, int n) {
    int w = (blockIdx.x * blockDim.x + threadIdx.x) >> 5;
    if (w >= n) return;
    int l = threadIdx.x & 31;
    int h0 = l >> 3;
    int hh = l & 7;
    float alDh = g_alD1[w * 8 + hh];
    int beg = g_rowstart[w], end = g_rowstart[w + 1];
    float acc0 = 0.f, acc1 = 0.f, qsum = 0.f;
    {
        float a = g_alS1[w * 8 + hh] + alDh;
        a = a > 0.f ? a : NEG * a;
        float q = __expf(a);
        if (l < 8) qsum += q;
        float p0 = __shfl_sync(0xFFFFFFFFu, q, h0);
        float p1 = __shfl_sync(0xFFFFFFFFu, q, h0 + 4);
        acc0 += p0 * g_h1[w * HID + l];
        acc1 += p1 * g_h1[w * HID + 32 + l];
    }
    for (int j = beg; j < end; j += 4) {
        int jj = j + h0;
        bool valid = jj < end;
        int srcv = g_eidx[valid ? jj : j];
        float a = g_alS1[srcv * 8 + hh] + alDh;
        a = a > 0.f ? a : NEG * a;
        float q = valid ? __expf(a) : 0.f;
        qsum += q;
        int nleft = end - j;
#pragma unroll
        for (int e2 = 0; e2 < 4; e2++) {
            if (e2 >= nleft) break;
            float p0 = __shfl_sync(0xFFFFFFFFu, q, e2 * 8 + h0);
            float p1 = __shfl_sync(0xFFFFFFFFu, q, e2 * 8 + h0 + 4);
            int sv = __shfl_sync(0xFFFFFFFFu, srcv, e2 * 8);
            acc0 += p0 * g_h1[sv * HID + l];
            acc1 += p1 * g_h1[sv * HID + 32 + l];
        }
    }
    qsum += __shfl_xor_sync(0xFFFFFFFFu, qsum, 8);
    qsum += __shfl_xor_sync(0xFFFFFFFFu, qsum, 16);
    float s0 = __shfl_sync(0xFFFFFFFFu, qsum, h0);
    float s1 = __shfl_sync(0xFFFFFFFFu, qsum, h0 + 4);
    float v0 = acc0 / s0 + b1[l];
    float v1 = acc1 / s1 + b1[32 + l];
    g_hact[w * HID + l]      = v0 > 0.f ? v0 : expm1f(v0);
    g_hact[w * HID + 32 + l] = v1 > 0.f ? v1 : expm1f(v1);
}

// ---------------- layer 2 GEMM (R5) ----------------
__global__ __launch_bounds__(160) void gemm2_k(
        const float* __restrict__ W2,
        const float* __restrict__ a_src2, const float* __restrict__ a_dst2, int n) {
    __shared__ float sW[HID * C2];
    __shared__ float sX[64 * HID];
    __shared__ float sLS[64];
    __shared__ float sLD[64];
    int t = threadIdx.x;
    int row0 = blockIdx.x * 64;
    for (int i = t; i < HID * C2; i += 160) sW[i] = W2[i];
    for (int i = t; i < 64 * HID; i += 160) {
        int r = i >> 6, c = i & 63;
        int gr = row0 + r;
        sX[i] = (gr < n) ? g_hact[gr * HID + c] : 0.f;
    }
    if (t < 64) { sLS[t] = 0.f; sLD[t] = 0.f; }
    __syncthreads();

    int cg = t % 10;
    int rg = t / 10;
    float acc[4][4];
#pragma unroll
    for (int r = 0; r < 4; r++)
#pragma unroll
        for (int c = 0; c < 4; c++) acc[r][c] = 0.f;

    const float4* sW4 = reinterpret_cast<const float4*>(sW);
#pragma unroll 4
    for (int k = 0; k < HID; k++) {
        float4 wv = sW4[k * 10 + cg];
        float xv0 = sX[(rg * 4 + 0) * HID + k];
        float xv1 = sX[(rg * 4 + 1) * HID + k];
        float xv2 = sX[(rg * 4 + 2) * HID + k];
        float xv3 = sX[(rg * 4 + 3) * HID + k];
#define STEP(r, xv) \
        acc[r][0] += xv * wv.x; acc[r][1] += xv * wv.y; \
        acc[r][2] += xv * wv.z; acc[r][3] += xv * wv.w;
        STEP(0, xv0) STEP(1, xv1) STEP(2, xv2) STEP(3, xv3)
#undef STEP
    }

#pragma unroll
    for (int r = 0; r < 4; r++) {
        int lr = rg * 4 + r;
        int gr = row0 + lr;
        float ps = 0.f, pd = 0.f;
#pragma unroll
        for (int j = 0; j < 4; j++) {
            int c = cg * 4 + j;
            if (gr < n) g_h2[gr * C2 + c] = acc[r][j];
            ps += acc[r][j] * a_src2[c];
            pd += acc[r][j] * a_dst2[c];
        }
        atomicAdd(&sLS[lr], ps);
        atomicAdd(&sLD[lr], pd);
    }
    __syncthreads();
    if (t < 64) {
        int gr = row0 + t;
        if (gr < n) { g_alS2[gr] = sLS[t]; g_alD2[gr] = sLD[t]; }
    }
}

// ---------------- layer 2 aggregation + log_softmax (R5) ----------------
__global__ __launch_bounds__(256) void agg2_k(const float* __restrict__ b2,
                                              float* __restrict__ out, int n) {
    int w = (blockIdx.x * blockDim.x + threadIdx.x) >> 5;
    if (w >= n) return;
    int l = threadIdx.x & 31;
    float alDv = g_alD2[w];
    int beg = g_rowstart[w], end = g_rowstart[w + 1];
    float acc0 = 0.f, acc1 = 0.f, ssum = 0.f;
    {
        float e = g_alS2[w] + alDv;
        e = e > 0.f ? e : NEG * e;
        float p = __expf(e);
        if (l == 0) ssum += p;
        acc0 += p * g_h2[w * C2 + l];
        if (l < 8) acc1 += p * g_h2[w * C2 + 32 + l];
    }
    for (int j = beg; j < end; j += 32) {
        int jj = j + l;
        bool valid = jj < end;
        int srcv = g_eidx[valid ? jj : j];
        float e = g_alS2[srcv] + alDv;
        e = e > 0.f ? e : NEG * e;
        float q = valid ? __expf(e) : 0.f;
        ssum += q;
        int m = min(32, end - j);
        for (int e2 = 0; e2 < m; e2++) {
            float pp = __shfl_sync(0xFFFFFFFFu, q, e2);
            int sv = __shfl_sync(0xFFFFFFFFu, srcv, e2);
            acc0 += pp * g_h2[sv * C2 + l];
            if (l < 8) acc1 += pp * g_h2[sv * C2 + 32 + l];
        }
    }
#pragma unroll
    for (int o = 16; o; o >>= 1) ssum += __shfl_xor_sync(0xFFFFFFFFu, ssum, o);
    float inv = 1.f / ssum;
    float v0 = acc0 * inv + b2[l];
    float v1 = (l < 8) ? (acc1 * inv + b2[32 + l]) : -3.0e38f;
    float m = fmaxf(v0, v1);
#pragma unroll
    for (int o = 16; o; o >>= 1) m = fmaxf(m, __shfl_xor_sync(0xFFFFFFFFu, m, o));
    float se = __expf(v0 - m) + ((l < 8) ? __expf(v1 - m) : 0.f);
#pragma unroll
    for (int o = 16; o; o >>= 1) se += __shfl_xor_sync(0xFFFFFFFFu, se, o);
    float lse = logf(se) + m;
    out[w * C2 + l] = v0 - lse;
    if (l < 8) out[w * C2 + 32 + l] = v1 - lse;
}

// ---------------- launcher ----------------
extern "C" void kernel_launch(void* const* d_in, const int* in_sizes, int n_in,
                              void* d_out, int out_size) {
    const float* x    = (const float*)d_in[0];
    const float* topo = (const float*)d_in[1];
    const int*   ei   = (const int*)d_in[2];
    const float* W1   = (const float*)d_in[3];
    const float* a_s1 = (const float*)d_in[4];
    const float* a_d1 = (const float*)d_in[5];
    const float* b1   = (const float*)d_in[6];
    const float* W2   = (const float*)d_in[7];
    const float* a_s2 = (const float*)d_in[8];
    const float* a_d2 = (const float*)d_in[9];
    const float* b2   = (const float*)d_in[10];
    float* out = (float*)d_out;

    int n = in_sizes[0] / 120;
    int E = in_sizes[2] / 2;
    int nb = (n + 1023) >> 10;

    const int GEMM1_SMEM = (8192 + 2 * 64 * SXCH + 1024) * 4;   // 55296 B
    cudaFuncSetAttribute(gemm1_k, cudaFuncAttributeMaxDynamicSharedMemorySize, GEMM1_SMEM);

    // gemm1 placed 4th (ncu capture slot)
    count_k<<<(E + 255) / 256, 256>>>(ei, E);
    scanA_k<<<nb, 1024>>>(n);
    scanC_k<<<(n + 255) / 256, 256>>>(n, E, nb);
    gemm1_k<<<(n + 63) / 64, 256, GEMM1_SMEM>>>(x, topo, W1, a_s1, a_d1, n);
    scatter_k<<<(E + 255) / 256, 256>>>(ei, E);
    agg1_k<<<(n * 32 + 255) / 256, 256>>>(b1, n);
    gemm2_k<<<(n + 63) / 64, 160>>>(W2, a_s2, a_d2, n);
    agg2_k<<<(n * 32 + 255) / 256, 256>>>(b2, out, n);
}